// round 13
// baseline (speedup 1.0000x reference)
#include <cuda_runtime.h>
#include <cuda_bf16.h>

#define BB 8
#define CC 512
#define DD 64
#define NN 4096
#define KSPLIT 8      // k2 split-K over n

// Scratch (device globals). ~17 MB.
__device__ unsigned g_QfP[BB * 32 * NN];            // delu(Q) bf16 pairs [b][d/2][n]
__device__ __nv_bfloat16 g_Kf[BB * DD * NN];        // delu(K) [b][d][n]
__device__ float g_Ksum[BB * DD];
__device__ __nv_bfloat16 g_KXpB[KSPLIT * BB * DD * CC];  // bf16 split-K partials
__device__ __nv_bfloat16 g_KVT[BB * CC * DD];       // final KV^T [b][c][d]

__device__ __forceinline__ float delu_f(float v) {
    return v > 0.f ? fmaf(10.f, v, 1.f) : __expf(10.f * v);
}
__device__ __forceinline__ float tf32_rna(float f) {
    unsigned u;
    asm("cvt.rna.tf32.f32 %0, %1;" : "=r"(u) : "f"(f));
    return __uint_as_float(u);
}
__device__ __forceinline__ unsigned packbf(float lo, float hi) {
    __nv_bfloat162 h = __floats2bfloat162_rn(lo, hi);
    return *(unsigned*)&h;
}
// tf32 m16n8k8
__device__ __forceinline__ void mma8(float c[4], float a0, float a1, float a2, float a3,
                                     float b0, float b1) {
    unsigned A0 = __float_as_uint(a0), A1 = __float_as_uint(a1);
    unsigned A2 = __float_as_uint(a2), A3 = __float_as_uint(a3);
    unsigned B0 = __float_as_uint(b0), B1 = __float_as_uint(b1);
    asm volatile(
        "mma.sync.aligned.m16n8k8.row.col.f32.tf32.tf32.f32 "
        "{%0,%1,%2,%3}, {%4,%5,%6,%7}, {%8,%9}, {%0,%1,%2,%3};"
        : "+f"(c[0]), "+f"(c[1]), "+f"(c[2]), "+f"(c[3])
        : "r"(A0), "r"(A1), "r"(A2), "r"(A3), "r"(B0), "r"(B1));
}
// bf16 m16n8k16
__device__ __forceinline__ void mma16(float c[4], unsigned a0, unsigned a1,
                                      unsigned a2, unsigned a3,
                                      unsigned b0, unsigned b1) {
    asm volatile(
        "mma.sync.aligned.m16n8k16.row.col.f32.bf16.bf16.f32 "
        "{%0,%1,%2,%3}, {%4,%5,%6,%7}, {%8,%9}, {%0,%1,%2,%3};"
        : "+f"(c[0]), "+f"(c[1]), "+f"(c[2]), "+f"(c[3])
        : "r"(a0), "r"(a1), "r"(a2), "r"(a3), "r"(b0), "r"(b1));
}

// ---------------------------------------------------------------------------
// K1 (bf16, fused Q+K + Ksum): [wq;wk](128x512) @ X(512x4096) + bias -> delu
// Block 128x128, Kchunk=32, 16 iters, 8 warps (2Mx4N). grid (32, 8).
// Ping-pong double buffered. Buf (u32) = 4736; 37,888 B dynamic smem.
// ---------------------------------------------------------------------------
#define K1_BUF 4736
__global__ __launch_bounds__(256, 2) void k1_qk(
    const float* __restrict__ x,  const float* __restrict__ wq,
    const float* __restrict__ bq, const float* __restrict__ wk,
    const float* __restrict__ bk)
{
    extern __shared__ unsigned su[];
    const int b = blockIdx.y;
    const int n0 = blockIdx.x * 128;
    const int tid = threadIdx.x, wid = tid >> 5, lane = tid & 31;
    const int lrow = lane >> 2, lcol = lane & 3;
    const int m0w = (wid >> 2) * 64, n0w = (wid & 3) * 32;

    float acc[4][4][4];
    #pragma unroll
    for (int i = 0; i < 4; i++)
        #pragma unroll
        for (int j = 0; j < 4; j++)
            #pragma unroll
            for (int u = 0; u < 4; u++) acc[i][j][u] = 0.f;

    const float* xb = x + (size_t)b * CC * NN;
    const int arow = tid >> 1, ak16 = (tid & 1) * 16;
    const float* wrow = (arow < 64) ? (wq + (size_t)arow * CC)
                                    : (wk + (size_t)(arow - 64) * CC);

    float4 pa[4];
    float4 pb[2][2];
    auto ldTiles = [&](int k0) {
        #pragma unroll
        for (int t = 0; t < 4; t++)
            pa[t] = *(const float4*)(wrow + k0 + ak16 + 4 * t);
        #pragma unroll
        for (int r = 0; r < 2; r++) {
            int idx = tid + r * 256;
            int kk = idx >> 5, nch = idx & 31;
            pb[r][0] = *(const float4*)(xb + (size_t)(k0 + 2 * kk) * NN + n0 + 4 * nch);
            pb[r][1] = *(const float4*)(xb + (size_t)(k0 + 2 * kk + 1) * NN + n0 + 4 * nch);
        }
    };
    auto stTiles = [&](unsigned* buf) {
        unsigned* A = buf; unsigned* B = buf + 2560;
        const float* f = (const float*)pa;
        unsigned wa[8];
        #pragma unroll
        for (int t = 0; t < 8; t++) wa[t] = packbf(f[2 * t], f[2 * t + 1]);
        *(uint4*)(A + arow * 20 + (tid & 1) * 8)     = *(uint4*)&wa[0];
        *(uint4*)(A + arow * 20 + (tid & 1) * 8 + 4) = *(uint4*)&wa[4];
        #pragma unroll
        for (int r = 0; r < 2; r++) {
            int idx = tid + r * 256;
            int kk = idx >> 5, nch = idx & 31;
            const float* fa = (const float*)&pb[r][0];
            const float* fb = (const float*)&pb[r][1];
            unsigned wb[4];
            #pragma unroll
            for (int t = 0; t < 4; t++) wb[t] = packbf(fa[t], fb[t]);
            *(uint4*)(B + kk * 136 + nch * 4) = *(uint4*)&wb[0];
        }
    };

    ldTiles(0);
    stTiles(su);
    __syncthreads();

    int ph = 0;
    for (int k0 = 0; k0 < CC; k0 += 32, ph ^= 1) {
        unsigned* cur = su + ph * K1_BUF;
        unsigned* nxt = su + (ph ^ 1) * K1_BUF;
        const bool more = (k0 + 32 < CC);
        if (more) ldTiles(k0 + 32);

        unsigned* A = cur; unsigned* B = cur + 2560;
        #pragma unroll
        for (int s = 0; s < 2; s++) {
            unsigned a[4][4], bb[4][2];
            #pragma unroll
            for (int i = 0; i < 4; i++) {
                int r0 = (m0w + 16 * i + lrow) * 20 + 8 * s;
                a[i][0] = A[r0 + lcol];       a[i][1] = A[r0 + 160 + lcol];
                a[i][2] = A[r0 + lcol + 4];   a[i][3] = A[r0 + 160 + lcol + 4];
            }
            #pragma unroll
            for (int j = 0; j < 4; j++) {
                int n = n0w + 8 * j + lrow;
                bb[j][0] = B[(8 * s + lcol) * 136 + n];
                bb[j][1] = B[(8 * s + lcol + 4) * 136 + n];
            }
            #pragma unroll
            for (int i = 0; i < 4; i++)
                #pragma unroll
                for (int j = 0; j < 4; j++)
                    mma16(acc[i][j], a[i][0], a[i][1], a[i][2], a[i][3], bb[j][0], bb[j][1]);
        }
        if (more) stTiles(nxt);
        __syncthreads();
    }

    const bool isK = (m0w == 64);
    #pragma unroll
    for (int i = 0; i < 4; i++) {
        int m = m0w + 16 * i + lrow;
        int mm = m & 63;
        float bi0 = isK ? bk[mm] : bq[mm];
        float bi1 = isK ? bk[mm + 8] : bq[mm + 8];
        float ks_lo = 0.f, ks_hi = 0.f;
        #pragma unroll
        for (int j = 0; j < 4; j++) {
            int n = n0 + n0w + 8 * j + 2 * lcol;
            float d0 = delu_f(acc[i][j][0] + bi0);
            float d1 = delu_f(acc[i][j][1] + bi0);
            float d2 = delu_f(acc[i][j][2] + bi1);
            float d3 = delu_f(acc[i][j][3] + bi1);
            if (isK) {
                __nv_bfloat16* dst = g_Kf + (size_t)b * DD * NN;
                *(__nv_bfloat162*)(dst + (size_t)mm * NN + n) = __floats2bfloat162_rn(d0, d1);
                *(__nv_bfloat162*)(dst + (size_t)(mm + 8) * NN + n) = __floats2bfloat162_rn(d2, d3);
                ks_lo += d0 + d1;
                ks_hi += d2 + d3;
            } else {
                float e0 = __shfl_xor_sync(0xFFFFFFFFu, d0, 4);
                float e1 = __shfl_xor_sync(0xFFFFFFFFu, d1, 4);
                float e2 = __shfl_xor_sync(0xFFFFFFFFu, d2, 4);
                float e3 = __shfl_xor_sync(0xFFFFFFFFu, d3, 4);
                unsigned w0, w1;
                int dp;
                if ((lrow & 1) == 0) {
                    w0 = packbf(d0, e0); w1 = packbf(d1, e1);
                    dp = mm >> 1;
                } else {
                    w0 = packbf(e2, d2); w1 = packbf(e3, d3);
                    dp = ((mm - 1) >> 1) + 4;
                }
                uint2 v; v.x = w0; v.y = w1;
                *(uint2*)(g_QfP + (size_t)b * 32 * NN + (size_t)dp * NN + n) = v;
            }
        }
        if (isK) {
            ks_lo += __shfl_xor_sync(0xFFFFFFFFu, ks_lo, 1);
            ks_lo += __shfl_xor_sync(0xFFFFFFFFu, ks_lo, 2);
            ks_hi += __shfl_xor_sync(0xFFFFFFFFu, ks_hi, 1);
            ks_hi += __shfl_xor_sync(0xFFFFFFFFu, ks_hi, 2);
            if (lcol == 0) {
                atomicAdd(&g_Ksum[b * DD + mm], ks_lo);
                atomicAdd(&g_Ksum[b * DD + mm + 8], ks_hi);
            }
        }
    }
}

// ---------------------------------------------------------------------------
// K2 (bf16): KXpB[s][b][d][e] (bf16) = sum_{n in split} Kf[d][n]*x[e][n]
// Block 64x128(e), Kchunk=64 halves, K=512/split (8 iters). grid (4, 8, 8)=256.
// Buf=6912 u32; double buffer 55,296 B. Ping-pong, one sync per iter.
// ---------------------------------------------------------------------------
#define K2_BUF 6912
__global__ __launch_bounds__(256, 2) void k2_kx(const float* __restrict__ x)
{
    extern __shared__ unsigned su[];
    const int e0 = blockIdx.x * 128, b = blockIdx.y, sp = blockIdx.z;
    const int nbase = sp * (NN / KSPLIT);
    const int tid = threadIdx.x, wid = tid >> 5, lane = tid & 31;
    const int lrow = lane >> 2, lcol = lane & 3;
    const int m0w = (wid >> 2) * 32, e0w = (wid & 3) * 32;

    float acc[2][4][4];
    #pragma unroll
    for (int i = 0; i < 2; i++)
        #pragma unroll
        for (int j = 0; j < 4; j++)
            #pragma unroll
            for (int u = 0; u < 4; u++) acc[i][j][u] = 0.f;

    const __nv_bfloat16* kf = g_Kf + (size_t)b * DD * NN + nbase;
    const float* xb = x + (size_t)b * CC * NN + nbase;
    const int ad = tid >> 3, ach = tid & 7;
    const int be = tid >> 4, bf4 = tid & 15;

    uint4 pa[2];
    unsigned pbu[8][2];
    auto ldTiles = [&](int k0) {
        pa[0] = *(const uint4*)(kf + (size_t)ad * NN + k0 + ach * 8);
        pa[1] = *(const uint4*)(kf + (size_t)(ad + 32) * NN + k0 + ach * 8);
        #pragma unroll
        for (int r = 0; r < 8; r++) {
            float4 v = *(const float4*)(xb + (size_t)(e0 + be + 16 * r) * NN + k0 + bf4 * 4);
            pbu[r][0] = packbf(v.x, v.y);
            pbu[r][1] = packbf(v.z, v.w);
        }
    };
    auto stTiles = [&](unsigned* buf) {
        unsigned* As = buf; unsigned* Bs = buf + 2304;
        *(uint4*)(As + ad * 36 + ach * 4)        = pa[0];
        *(uint4*)(As + (ad + 32) * 36 + ach * 4) = pa[1];
        #pragma unroll
        for (int r = 0; r < 8; r++) {
            Bs[(be + 16 * r) * 36 + bf4 * 2]     = pbu[r][0];
            Bs[(be + 16 * r) * 36 + bf4 * 2 + 1] = pbu[r][1];
        }
    };

    ldTiles(0);
    stTiles(su);
    __syncthreads();

    int ph = 0;
    for (int k0 = 0; k0 < NN / KSPLIT; k0 += 64, ph ^= 1) {
        unsigned* cur = su + ph * K2_BUF;
        unsigned* nxt = su + (ph ^ 1) * K2_BUF;
        const bool more = (k0 + 64 < NN / KSPLIT);
        if (more) ldTiles(k0 + 64);

        unsigned* As = cur; unsigned* Bs = cur + 2304;
        #pragma unroll
        for (int s = 0; s < 4; s++) {
            unsigned a[2][4], bb[4][2];
            #pragma unroll
            for (int i = 0; i < 2; i++) {
                int r0 = (m0w + 16 * i + lrow) * 36 + 8 * s + lcol;
                a[i][0] = As[r0];           a[i][1] = As[r0 + 288];
                a[i][2] = As[r0 + 4];       a[i][3] = As[r0 + 292];
            }
            #pragma unroll
            for (int j = 0; j < 4; j++) {
                int er = (e0w + 8 * j + lrow) * 36 + 8 * s + lcol;
                bb[j][0] = Bs[er]; bb[j][1] = Bs[er + 4];
            }
            #pragma unroll
            for (int i = 0; i < 2; i++)
                #pragma unroll
                for (int j = 0; j < 4; j++)
                    mma16(acc[i][j], a[i][0], a[i][1], a[i][2], a[i][3], bb[j][0], bb[j][1]);
        }
        if (more) stTiles(nxt);
        __syncthreads();
    }

    // bf16 partial store: e pairs (e, e+1) pack into one u32.
    __nv_bfloat16* dst = g_KXpB + (size_t)(sp * BB + b) * DD * CC;
    #pragma unroll
    for (int i = 0; i < 2; i++) {
        int d = m0w + 16 * i + lrow;
        #pragma unroll
        for (int j = 0; j < 4; j++) {
            int e = e0 + e0w + 8 * j + 2 * lcol;
            *(unsigned*)(dst + (size_t)d * CC + e)       = packbf(acc[i][j][0], acc[i][j][1]);
            *(unsigned*)(dst + (size_t)(d + 8) * CC + e) = packbf(acc[i][j][2], acc[i][j][3]);
        }
    }
}

// ---------------------------------------------------------------------------
// K3 (tf32, single finisher): KVT[b][c][d] (bf16) =
//     sum_e (sum_sp KXpB[sp][b][d][e]) * wv[c][e] + bv[c]*Ksum[b][d]
// grid (CC/32=16, BB) = 128 blocks, 256 thr. Block output: 64d x 32c.
// e-loop: 8 iters of 64. KXpB (4 MB) is L2-resident; re-read 16x = 64 MB L2.
// 8 warps: dw = wid>>2 (2 x 32d), cw = wid&3 (4 x 8c). acc[2][4] per warp.
// ---------------------------------------------------------------------------
__global__ __launch_bounds__(256) void k3_kv(
    const float* __restrict__ wv, const float* __restrict__ bv)
{
    __shared__ float As[64 * 68];    // [d][e-chunk 64] tf32
    __shared__ float Bs[32 * 68];    // [c][e-chunk 64] tf32
    __shared__ float S[64 * 33];     // [d][c] result staging
    __shared__ float ksS[64];
    __shared__ float bvS[32];
    const int c0 = blockIdx.x * 32, b = blockIdx.y;
    const int tid = threadIdx.x, wid = tid >> 5, lane = tid & 31;
    const int lrow = lane >> 2, lcol = lane & 3;
    const int m0w = (wid >> 2) * 32;   // d-tile base (0 or 32)
    const int cw = wid & 3;            // c-tile base cw*8

    if (tid < 64) ksS[tid] = g_Ksum[b * DD + tid];
    else if (tid >= 64 && tid < 96) bvS[tid - 64] = bv[c0 + tid - 64];

    float acc[2][4];
    #pragma unroll
    for (int i = 0; i < 2; i++)
        #pragma unroll
        for (int u = 0; u < 4; u++) acc[i][u] = 0.f;

    for (int ec = 0; ec < 8; ec++) {
        const int ebase = ec * 64;
        __syncthreads();   // As/Bs free (prior iter mma done); 1st iter: ks/bv ready
        // As: sum 8 bf16 partials -> tf32. 64d x 16 chunks(4e) = 1024 pos, 4/thread.
        #pragma unroll
        for (int r = 0; r < 4; r++) {
            int idx = tid + r * 256;
            int d = idx >> 4, ch = (idx & 15) * 4;
            float s0 = 0.f, s1 = 0.f, s2 = 0.f, s3 = 0.f;
            #pragma unroll
            for (int sp = 0; sp < KSPLIT; sp++) {
                uint2 v = *(const uint2*)(g_KXpB +
                    ((size_t)(sp * BB + b) * DD + d) * CC + ebase + ch);
                float2 f0 = __bfloat1622float2(*(const __nv_bfloat162*)&v.x);
                float2 f1 = __bfloat1622float2(*(const __nv_bfloat162*)&v.y);
                s0 += f0.x; s1 += f0.y; s2 += f1.x; s3 += f1.y;
            }
            As[d * 68 + ch + 0] = tf32_rna(s0);
            As[d * 68 + ch + 1] = tf32_rna(s1);
            As[d * 68 + ch + 2] = tf32_rna(s2);
            As[d * 68 + ch + 3] = tf32_rna(s3);
        }
        // Bs: wv[32c x 64e] -> tf32. 512 pos, 2/thread.
        #pragma unroll
        for (int r = 0; r < 2; r++) {
            int idx = tid + r * 256;
            int c = idx >> 4, ch = (idx & 15) * 4;
            float4 v = *(const float4*)(wv + (size_t)(c0 + c) * CC + ebase + ch);
            Bs[c * 68 + ch + 0] = tf32_rna(v.x);
            Bs[c * 68 + ch + 1] = tf32_rna(v.y);
            Bs[c * 68 + ch + 2] = tf32_rna(v.z);
            Bs[c * 68 + ch + 3] = tf32_rna(v.w);
        }
        __syncthreads();

        #pragma unroll
        for (int s = 0; s < 8; s++) {
            float a[2][4], bb[2];
            #pragma unroll
            for (int i = 0; i < 2; i++) {
                int r0 = (m0w + 16 * i + lrow) * 68, cc0 = 8 * s + lcol;
                a[i][0] = As[r0 + cc0];           a[i][1] = As[r0 + 8 * 68 + cc0];
                a[i][2] = As[r0 + cc0 + 4];       a[i][3] = As[r0 + 8 * 68 + cc0 + 4];
            }
            int cr = (cw * 8 + lrow) * 68;
            bb[0] = Bs[cr + 8 * s + lcol];
            bb[1] = Bs[cr + 8 * s + lcol + 4];
            #pragma unroll
            for (int i = 0; i < 2; i++)
                mma8(acc[i], a[i][0], a[i][1], a[i][2], a[i][3], bb[0], bb[1]);
        }
    }

    // Stage D[64d][32c] in smem.
    #pragma unroll
    for (int i = 0; i < 2; i++) {
        int d = m0w + 16 * i + lrow;
        int c = cw * 8 + 2 * lcol;
        S[d * 33 + c]           = acc[i][0];
        S[d * 33 + c + 1]       = acc[i][1];
        S[(d + 8) * 33 + c]     = acc[i][2];
        S[(d + 8) * 33 + c + 1] = acc[i][3];
    }
    __syncthreads();

    // Transposed bf16 write with bias: 32c x 8 d-chunks, 1 uint4/thread.
    {
        int c = tid >> 3, dch = tid & 7;
        int d0 = dch * 8;
        float bvv = bvS[c];
        unsigned w[4];
        #pragma unroll
        for (int u = 0; u < 4; u++) {
            float v0 = S[(d0 + 2 * u) * 33 + c]     + bvv * ksS[d0 + 2 * u];
            float v1 = S[(d0 + 2 * u + 1) * 33 + c] + bvv * ksS[d0 + 2 * u + 1];
            w[u] = packbf(v0, v1);
        }
        uint4 vv; vv.x = w[0]; vv.y = w[1]; vv.z = w[2]; vv.w = w[3];
        *(uint4*)(g_KVT + ((size_t)b * CC + c0 + c) * DD + d0) = vv;
    }
}

// ---------------------------------------------------------------------------
// K4 (bf16): out[c][n] = x[c][n] + gamma*norm[n]*sum_d KVT[c][d]*QfP[d][n]
// Persistent over c: grid (32, 8) = 256 blocks, occ 2. 8 warps: 4Mx2N.
// ---------------------------------------------------------------------------
__global__ __launch_bounds__(256, 2) void k4_out(
    const float* __restrict__ x, const float* __restrict__ gamma,
    float* __restrict__ out)
{
    __shared__ __align__(16) unsigned As32[128 * 36];
    __shared__ __align__(16) unsigned Bs32[128 * 36];
    __shared__ float ksumS[64];
    __shared__ float normS[128];

    const int n0 = blockIdx.x * 128, b = blockIdx.y;
    const int tid = threadIdx.x, wid = tid >> 5, lane = tid & 31;
    const int lrow = lane >> 2, lcol = lane & 3;
    const int m0w = (wid >> 1) * 32, n0w = (wid & 1) * 64;

    const unsigned* qfp = g_QfP + (size_t)b * 32 * NN;
    const __nv_bfloat16* kvt = g_KVT + (size_t)b * CC * DD;

    #pragma unroll
    for (int r = 0; r < 16; r++) {
        int idx = tid + r * 256;
        int dlo = idx & 3, nlo = (idx >> 2) & 7;
        int dhi = (idx >> 5) & 7, nhi = idx >> 8;
        int dp = dhi * 4 + dlo, n = nhi * 8 + nlo;
        Bs32[n * 36 + dp] = qfp[(size_t)dp * NN + n0 + n];
    }
    if (tid < 64) ksumS[tid] = g_Ksum[b * DD + tid] + 1e-10f;

    uint4 kvreg[4];
    auto ldKV = [&](int c0) {
        #pragma unroll
        for (int r = 0; r < 4; r++) {
            int idx = tid + r * 256;
            int c = idx >> 3, ch = idx & 7;
            kvreg[r] = *(const uint4*)(kvt + (size_t)(c0 + c) * DD + ch * 8);
        }
    };
    auto stAs = [&]() {
        #pragma unroll
        for (int r = 0; r < 4; r++) {
            int idx = tid + r * 256;
            int c = idx >> 3, ch = idx & 7;
            *(uint4*)(As32 + c * 36 + ch * 4) = kvreg[r];
        }
    };

    ldKV(0);
    __syncthreads();

    if (tid < 128) {
        float s = 0.f;
        #pragma unroll
        for (int dp = 0; dp < 32; dp++) {
            float2 f = __bfloat1622float2(*(const __nv_bfloat162*)&Bs32[tid * 36 + dp]);
            s = fmaf(f.x, ksumS[2 * dp], s);
            s = fmaf(f.y, ksumS[2 * dp + 1], s);
        }
        normS[tid] = 1.0f / s;
    }
    const float g = gamma[0];

    for (int ct = 0; ct < CC / 128; ct++) {
        const int c0 = ct * 128;
        __syncthreads();
        stAs();
        __syncthreads();
        if (ct + 1 < CC / 128) ldKV(c0 + 128);

        float acc[2][8][4];
        #pragma unroll
        for (int i = 0; i < 2; i++)
            #pragma unroll
            for (int j = 0; j < 8; j++)
                #pragma unroll
                for (int u = 0; u < 4; u++) acc[i][j][u] = 0.f;

        #pragma unroll
        for (int s = 0; s < 4; s++) {
            unsigned a[2][4], bb[8][2];
            #pragma unroll
            for (int i = 0; i < 2; i++) {
                int r0 = (m0w + 16 * i + lrow) * 36 + 8 * s + lcol;
                a[i][0] = As32[r0];       a[i][1] = As32[r0 + 288];
                a[i][2] = As32[r0 + 4];   a[i][3] = As32[r0 + 292];
            }
            #pragma unroll
            for (int j = 0; j < 8; j++) {
                int nr = (n0w + 8 * j + lrow) * 36 + 8 * s + lcol;
                bb[j][0] = Bs32[nr]; bb[j][1] = Bs32[nr + 4];
            }
            #pragma unroll
            for (int i = 0; i < 2; i++)
                #pragma unroll
                for (int j = 0; j < 8; j++)
                    mma16(acc[i][j], a[i][0], a[i][1], a[i][2], a[i][3], bb[j][0], bb[j][1]);
        }

        #pragma unroll
        for (int i = 0; i < 2; i++) {
            int c = c0 + m0w + 16 * i + lrow;
            #pragma unroll
            for (int j = 0; j < 8; j++) {
                int nl = n0w + 8 * j + 2 * lcol;
                int n = n0 + nl;
                float2 nr = *(float2*)&normS[nl];
                const float* xp0 = x + ((size_t)b * CC + c) * NN + n;
                float*       op0 = out + ((size_t)b * CC + c) * NN + n;
                float2 xv0 = *(const float2*)xp0;
                float2 o0 = { xv0.x + g * nr.x * acc[i][j][0],
                              xv0.y + g * nr.y * acc[i][j][1] };
                *(float2*)op0 = o0;
                const float* xp1 = x + ((size_t)b * CC + c + 8) * NN + n;
                float*       op1 = out + ((size_t)b * CC + c + 8) * NN + n;
                float2 xv1 = *(const float2*)xp1;
                float2 o1 = { xv1.x + g * nr.x * acc[i][j][2],
                              xv1.y + g * nr.y * acc[i][j][3] };
                *(float2*)op1 = o1;
            }
        }
    }
}

// ---------------------------------------------------------------------------
extern "C" void kernel_launch(void* const* d_in, const int* in_sizes, int n_in,
                              void* d_out, int out_size)
{
    const float* x     = (const float*)d_in[0];
    const float* wq    = (const float*)d_in[1];
    const float* bq    = (const float*)d_in[2];
    const float* wk    = (const float*)d_in[3];
    const float* bk    = (const float*)d_in[4];
    const float* wv    = (const float*)d_in[5];
    const float* bv    = (const float*)d_in[6];
    const float* gamma = (const float*)d_in[7];
    float* out = (float*)d_out;

    (void)in_sizes; (void)n_in; (void)out_size;

    cudaFuncSetAttribute(k1_qk, cudaFuncAttributeMaxDynamicSharedMemorySize, 37888);
    cudaFuncSetAttribute(k2_kx, cudaFuncAttributeMaxDynamicSharedMemorySize, 55296);

    void* ksum_ptr = nullptr;
    cudaGetSymbolAddress(&ksum_ptr, g_Ksum);
    cudaMemsetAsync(ksum_ptr, 0, BB * DD * sizeof(float));

    k1_qk <<<dim3(NN / 128, BB),          256, 37888>>>(x, wq, bq, wk, bk);
    k2_kx <<<dim3(CC / 128, BB, KSPLIT),  256, 55296>>>(x);
    k3_kv <<<dim3(CC / 32, BB),           256>>>(wv, bv);
    k4_out<<<dim3(NN / 128, BB),          256>>>(x, gamma, out);
}

// round 14
// speedup vs baseline: 1.0747x; 1.0747x over previous
#include <cuda_runtime.h>
#include <cuda_bf16.h>

#define BB 8
#define CC 512
#define DD 64
#define NN 4096
#define KSPLIT 8      // k2 split-K over n

// Scratch (device globals). ~14 MB.
__device__ unsigned g_QfP[BB * 32 * NN];            // delu(Q) bf16 pairs [b][d/2][n]
__device__ __nv_bfloat16 g_Kf[BB * DD * NN];        // delu(K) [b][d][n]
__device__ float g_Ksum[BB * DD];
__device__ float g_KX[BB * DD * CC];                // final Kf@X^T (atomic accum)
__device__ __nv_bfloat16 g_KVT[BB * CC * DD];       // final KV^T [b][c][d]

__device__ __forceinline__ float delu_f(float v) {
    return v > 0.f ? fmaf(10.f, v, 1.f) : __expf(10.f * v);
}
__device__ __forceinline__ float tf32_rna(float f) {
    unsigned u;
    asm("cvt.rna.tf32.f32 %0, %1;" : "=r"(u) : "f"(f));
    return __uint_as_float(u);
}
__device__ __forceinline__ unsigned packbf(float lo, float hi) {
    __nv_bfloat162 h = __floats2bfloat162_rn(lo, hi);
    return *(unsigned*)&h;
}
// tf32 m16n8k8
__device__ __forceinline__ void mma8(float c[4], float a0, float a1, float a2, float a3,
                                     float b0, float b1) {
    unsigned A0 = __float_as_uint(a0), A1 = __float_as_uint(a1);
    unsigned A2 = __float_as_uint(a2), A3 = __float_as_uint(a3);
    unsigned B0 = __float_as_uint(b0), B1 = __float_as_uint(b1);
    asm volatile(
        "mma.sync.aligned.m16n8k8.row.col.f32.tf32.tf32.f32 "
        "{%0,%1,%2,%3}, {%4,%5,%6,%7}, {%8,%9}, {%0,%1,%2,%3};"
        : "+f"(c[0]), "+f"(c[1]), "+f"(c[2]), "+f"(c[3])
        : "r"(A0), "r"(A1), "r"(A2), "r"(A3), "r"(B0), "r"(B1));
}
// bf16 m16n8k16
__device__ __forceinline__ void mma16(float c[4], unsigned a0, unsigned a1,
                                      unsigned a2, unsigned a3,
                                      unsigned b0, unsigned b1) {
    asm volatile(
        "mma.sync.aligned.m16n8k16.row.col.f32.bf16.bf16.f32 "
        "{%0,%1,%2,%3}, {%4,%5,%6,%7}, {%8,%9}, {%0,%1,%2,%3};"
        : "+f"(c[0]), "+f"(c[1]), "+f"(c[2]), "+f"(c[3])
        : "r"(a0), "r"(a1), "r"(a2), "r"(a3), "r"(b0), "r"(b1));
}

// ---------------------------------------------------------------------------
// K1 (bf16, fused Q+K + Ksum): [wq;wk](128x512) @ X(512x4096) + bias -> delu
// Block 128x128, Kchunk=32, 16 iters, 8 warps (2Mx4N). grid (32, 8).
// Ping-pong double buffered. Buf (u32) = 4736; 37,888 B dynamic smem.
// ---------------------------------------------------------------------------
#define K1_BUF 4736
__global__ __launch_bounds__(256, 2) void k1_qk(
    const float* __restrict__ x,  const float* __restrict__ wq,
    const float* __restrict__ bq, const float* __restrict__ wk,
    const float* __restrict__ bk)
{
    extern __shared__ unsigned su[];
    const int b = blockIdx.y;
    const int n0 = blockIdx.x * 128;
    const int tid = threadIdx.x, wid = tid >> 5, lane = tid & 31;
    const int lrow = lane >> 2, lcol = lane & 3;
    const int m0w = (wid >> 2) * 64, n0w = (wid & 3) * 32;

    float acc[4][4][4];
    #pragma unroll
    for (int i = 0; i < 4; i++)
        #pragma unroll
        for (int j = 0; j < 4; j++)
            #pragma unroll
            for (int u = 0; u < 4; u++) acc[i][j][u] = 0.f;

    const float* xb = x + (size_t)b * CC * NN;
    const int arow = tid >> 1, ak16 = (tid & 1) * 16;
    const float* wrow = (arow < 64) ? (wq + (size_t)arow * CC)
                                    : (wk + (size_t)(arow - 64) * CC);

    float4 pa[4];
    float4 pb[2][2];
    auto ldTiles = [&](int k0) {
        #pragma unroll
        for (int t = 0; t < 4; t++)
            pa[t] = *(const float4*)(wrow + k0 + ak16 + 4 * t);
        #pragma unroll
        for (int r = 0; r < 2; r++) {
            int idx = tid + r * 256;
            int kk = idx >> 5, nch = idx & 31;
            pb[r][0] = *(const float4*)(xb + (size_t)(k0 + 2 * kk) * NN + n0 + 4 * nch);
            pb[r][1] = *(const float4*)(xb + (size_t)(k0 + 2 * kk + 1) * NN + n0 + 4 * nch);
        }
    };
    auto stTiles = [&](unsigned* buf) {
        unsigned* A = buf; unsigned* B = buf + 2560;
        const float* f = (const float*)pa;
        unsigned wa[8];
        #pragma unroll
        for (int t = 0; t < 8; t++) wa[t] = packbf(f[2 * t], f[2 * t + 1]);
        *(uint4*)(A + arow * 20 + (tid & 1) * 8)     = *(uint4*)&wa[0];
        *(uint4*)(A + arow * 20 + (tid & 1) * 8 + 4) = *(uint4*)&wa[4];
        #pragma unroll
        for (int r = 0; r < 2; r++) {
            int idx = tid + r * 256;
            int kk = idx >> 5, nch = idx & 31;
            const float* fa = (const float*)&pb[r][0];
            const float* fb = (const float*)&pb[r][1];
            unsigned wb[4];
            #pragma unroll
            for (int t = 0; t < 4; t++) wb[t] = packbf(fa[t], fb[t]);
            *(uint4*)(B + kk * 136 + nch * 4) = *(uint4*)&wb[0];
        }
    };

    ldTiles(0);
    stTiles(su);
    __syncthreads();

    int ph = 0;
    for (int k0 = 0; k0 < CC; k0 += 32, ph ^= 1) {
        unsigned* cur = su + ph * K1_BUF;
        unsigned* nxt = su + (ph ^ 1) * K1_BUF;
        const bool more = (k0 + 32 < CC);
        if (more) ldTiles(k0 + 32);

        unsigned* A = cur; unsigned* B = cur + 2560;
        #pragma unroll
        for (int s = 0; s < 2; s++) {
            unsigned a[4][4], bb[4][2];
            #pragma unroll
            for (int i = 0; i < 4; i++) {
                int r0 = (m0w + 16 * i + lrow) * 20 + 8 * s;
                a[i][0] = A[r0 + lcol];       a[i][1] = A[r0 + 160 + lcol];
                a[i][2] = A[r0 + lcol + 4];   a[i][3] = A[r0 + 160 + lcol + 4];
            }
            #pragma unroll
            for (int j = 0; j < 4; j++) {
                int n = n0w + 8 * j + lrow;
                bb[j][0] = B[(8 * s + lcol) * 136 + n];
                bb[j][1] = B[(8 * s + lcol + 4) * 136 + n];
            }
            #pragma unroll
            for (int i = 0; i < 4; i++)
                #pragma unroll
                for (int j = 0; j < 4; j++)
                    mma16(acc[i][j], a[i][0], a[i][1], a[i][2], a[i][3], bb[j][0], bb[j][1]);
        }
        if (more) stTiles(nxt);
        __syncthreads();
    }

    const bool isK = (m0w == 64);
    #pragma unroll
    for (int i = 0; i < 4; i++) {
        int m = m0w + 16 * i + lrow;
        int mm = m & 63;
        float bi0 = isK ? bk[mm] : bq[mm];
        float bi1 = isK ? bk[mm + 8] : bq[mm + 8];
        float ks_lo = 0.f, ks_hi = 0.f;
        #pragma unroll
        for (int j = 0; j < 4; j++) {
            int n = n0 + n0w + 8 * j + 2 * lcol;
            float d0 = delu_f(acc[i][j][0] + bi0);
            float d1 = delu_f(acc[i][j][1] + bi0);
            float d2 = delu_f(acc[i][j][2] + bi1);
            float d3 = delu_f(acc[i][j][3] + bi1);
            if (isK) {
                __nv_bfloat16* dst = g_Kf + (size_t)b * DD * NN;
                *(__nv_bfloat162*)(dst + (size_t)mm * NN + n) = __floats2bfloat162_rn(d0, d1);
                *(__nv_bfloat162*)(dst + (size_t)(mm + 8) * NN + n) = __floats2bfloat162_rn(d2, d3);
                ks_lo += d0 + d1;
                ks_hi += d2 + d3;
            } else {
                float e0 = __shfl_xor_sync(0xFFFFFFFFu, d0, 4);
                float e1 = __shfl_xor_sync(0xFFFFFFFFu, d1, 4);
                float e2 = __shfl_xor_sync(0xFFFFFFFFu, d2, 4);
                float e3 = __shfl_xor_sync(0xFFFFFFFFu, d3, 4);
                unsigned w0, w1;
                int dp;
                if ((lrow & 1) == 0) {
                    w0 = packbf(d0, e0); w1 = packbf(d1, e1);
                    dp = mm >> 1;
                } else {
                    w0 = packbf(e2, d2); w1 = packbf(e3, d3);
                    dp = ((mm - 1) >> 1) + 4;
                }
                uint2 v; v.x = w0; v.y = w1;
                *(uint2*)(g_QfP + (size_t)b * 32 * NN + (size_t)dp * NN + n) = v;
            }
        }
        if (isK) {
            ks_lo += __shfl_xor_sync(0xFFFFFFFFu, ks_lo, 1);
            ks_lo += __shfl_xor_sync(0xFFFFFFFFu, ks_lo, 2);
            ks_hi += __shfl_xor_sync(0xFFFFFFFFu, ks_hi, 1);
            ks_hi += __shfl_xor_sync(0xFFFFFFFFu, ks_hi, 2);
            if (lcol == 0) {
                atomicAdd(&g_Ksum[b * DD + mm], ks_lo);
                atomicAdd(&g_Ksum[b * DD + mm + 8], ks_hi);
            }
        }
    }
}

// ---------------------------------------------------------------------------
// K2 (bf16): atomicAdd into g_KX[b][d][e] += sum_{n in split} Kf[d][n]*x[e][n]
// Block 64x128(e), Kchunk=64 halves, K=512/split (8 iters). grid (4, 8, 8)=256.
// Buf=6912 u32; double buffer 55,296 B. Ping-pong, one sync per iter.
// ---------------------------------------------------------------------------
#define K2_BUF 6912
__global__ __launch_bounds__(256, 2) void k2_kx(const float* __restrict__ x)
{
    extern __shared__ unsigned su[];
    const int e0 = blockIdx.x * 128, b = blockIdx.y, sp = blockIdx.z;
    const int nbase = sp * (NN / KSPLIT);
    const int tid = threadIdx.x, wid = tid >> 5, lane = tid & 31;
    const int lrow = lane >> 2, lcol = lane & 3;
    const int m0w = (wid >> 2) * 32, e0w = (wid & 3) * 32;

    float acc[2][4][4];
    #pragma unroll
    for (int i = 0; i < 2; i++)
        #pragma unroll
        for (int j = 0; j < 4; j++)
            #pragma unroll
            for (int u = 0; u < 4; u++) acc[i][j][u] = 0.f;

    const __nv_bfloat16* kf = g_Kf + (size_t)b * DD * NN + nbase;
    const float* xb = x + (size_t)b * CC * NN + nbase;
    const int ad = tid >> 3, ach = tid & 7;
    const int be = tid >> 4, bf4 = tid & 15;

    uint4 pa[2];
    unsigned pbu[8][2];
    auto ldTiles = [&](int k0) {
        pa[0] = *(const uint4*)(kf + (size_t)ad * NN + k0 + ach * 8);
        pa[1] = *(const uint4*)(kf + (size_t)(ad + 32) * NN + k0 + ach * 8);
        #pragma unroll
        for (int r = 0; r < 8; r++) {
            float4 v = *(const float4*)(xb + (size_t)(e0 + be + 16 * r) * NN + k0 + bf4 * 4);
            pbu[r][0] = packbf(v.x, v.y);
            pbu[r][1] = packbf(v.z, v.w);
        }
    };
    auto stTiles = [&](unsigned* buf) {
        unsigned* As = buf; unsigned* Bs = buf + 2304;
        *(uint4*)(As + ad * 36 + ach * 4)        = pa[0];
        *(uint4*)(As + (ad + 32) * 36 + ach * 4) = pa[1];
        #pragma unroll
        for (int r = 0; r < 8; r++) {
            Bs[(be + 16 * r) * 36 + bf4 * 2]     = pbu[r][0];
            Bs[(be + 16 * r) * 36 + bf4 * 2 + 1] = pbu[r][1];
        }
    };

    ldTiles(0);
    stTiles(su);
    __syncthreads();

    int ph = 0;
    for (int k0 = 0; k0 < NN / KSPLIT; k0 += 64, ph ^= 1) {
        unsigned* cur = su + ph * K2_BUF;
        unsigned* nxt = su + (ph ^ 1) * K2_BUF;
        const bool more = (k0 + 64 < NN / KSPLIT);
        if (more) ldTiles(k0 + 64);

        unsigned* As = cur; unsigned* Bs = cur + 2304;
        #pragma unroll
        for (int s = 0; s < 4; s++) {
            unsigned a[2][4], bb[4][2];
            #pragma unroll
            for (int i = 0; i < 2; i++) {
                int r0 = (m0w + 16 * i + lrow) * 36 + 8 * s + lcol;
                a[i][0] = As[r0];           a[i][1] = As[r0 + 288];
                a[i][2] = As[r0 + 4];       a[i][3] = As[r0 + 292];
            }
            #pragma unroll
            for (int j = 0; j < 4; j++) {
                int er = (e0w + 8 * j + lrow) * 36 + 8 * s + lcol;
                bb[j][0] = Bs[er]; bb[j][1] = Bs[er + 4];
            }
            #pragma unroll
            for (int i = 0; i < 2; i++)
                #pragma unroll
                for (int j = 0; j < 4; j++)
                    mma16(acc[i][j], a[i][0], a[i][1], a[i][2], a[i][3], bb[j][0], bb[j][1]);
        }
        if (more) stTiles(nxt);
        __syncthreads();
    }

    // Atomic accumulate into final KX (spread addresses; no partials array).
    float* dst = g_KX + (size_t)b * DD * CC;
    #pragma unroll
    for (int i = 0; i < 2; i++) {
        int d = m0w + 16 * i + lrow;
        #pragma unroll
        for (int j = 0; j < 4; j++) {
            int e = e0 + e0w + 8 * j + 2 * lcol;
            atomicAdd(dst + (size_t)d * CC + e,     acc[i][j][0]);
            atomicAdd(dst + (size_t)d * CC + e + 1, acc[i][j][1]);
            atomicAdd(dst + (size_t)(d + 8) * CC + e,     acc[i][j][2]);
            atomicAdd(dst + (size_t)(d + 8) * CC + e + 1, acc[i][j][3]);
        }
    }
}

// ---------------------------------------------------------------------------
// K3 (tf32 finisher): KVT[b][c][d] (bf16) =
//     sum_e KX[b][d][e] * wv[c][e] + bv[c]*Ksum[b][d]
// grid (CC/32=16, BB) = 128 blocks, 256 thr. Block output: 64d x 32c.
// e-loop: 8 iters of 64. KX (1 MB) is L2-resident; A-build is one fp32 stream.
// 8 warps: dw = wid>>2 (2 x 32d), cw = wid&3 (4 x 8c). acc[2][4] per warp.
// ---------------------------------------------------------------------------
__global__ __launch_bounds__(256) void k3_kv(
    const float* __restrict__ wv, const float* __restrict__ bv)
{
    __shared__ float As[64 * 68];    // [d][e-chunk 64] tf32
    __shared__ float Bs[32 * 68];    // [c][e-chunk 64] tf32
    __shared__ float S[64 * 33];     // [d][c] result staging
    __shared__ float ksS[64];
    __shared__ float bvS[32];
    const int c0 = blockIdx.x * 32, b = blockIdx.y;
    const int tid = threadIdx.x, wid = tid >> 5, lane = tid & 31;
    const int lrow = lane >> 2, lcol = lane & 3;
    const int m0w = (wid >> 2) * 32;   // d-tile base (0 or 32)
    const int cw = wid & 3;            // c-tile base cw*8

    if (tid < 64) ksS[tid] = g_Ksum[b * DD + tid];
    else if (tid >= 64 && tid < 96) bvS[tid - 64] = bv[c0 + tid - 64];

    float acc[2][4];
    #pragma unroll
    for (int i = 0; i < 2; i++)
        #pragma unroll
        for (int u = 0; u < 4; u++) acc[i][u] = 0.f;

    const float* kx = g_KX + (size_t)b * DD * CC;

    for (int ec = 0; ec < 8; ec++) {
        const int ebase = ec * 64;
        __syncthreads();   // As/Bs free (prior iter mma done); 1st iter: ks/bv ready
        // As: KX[64d x 64e] -> tf32. 1024 float4 positions, 4/thread.
        #pragma unroll
        for (int r = 0; r < 4; r++) {
            int idx = tid + r * 256;
            int d = idx >> 4, ch = (idx & 15) * 4;
            float4 v = *(const float4*)(kx + (size_t)d * CC + ebase + ch);
            As[d * 68 + ch + 0] = tf32_rna(v.x);
            As[d * 68 + ch + 1] = tf32_rna(v.y);
            As[d * 68 + ch + 2] = tf32_rna(v.z);
            As[d * 68 + ch + 3] = tf32_rna(v.w);
        }
        // Bs: wv[32c x 64e] -> tf32. 512 pos, 2/thread.
        #pragma unroll
        for (int r = 0; r < 2; r++) {
            int idx = tid + r * 256;
            int c = idx >> 4, ch = (idx & 15) * 4;
            float4 v = *(const float4*)(wv + (size_t)(c0 + c) * CC + ebase + ch);
            Bs[c * 68 + ch + 0] = tf32_rna(v.x);
            Bs[c * 68 + ch + 1] = tf32_rna(v.y);
            Bs[c * 68 + ch + 2] = tf32_rna(v.z);
            Bs[c * 68 + ch + 3] = tf32_rna(v.w);
        }
        __syncthreads();

        #pragma unroll
        for (int s = 0; s < 8; s++) {
            float a[2][4], bb[2];
            #pragma unroll
            for (int i = 0; i < 2; i++) {
                int r0 = (m0w + 16 * i + lrow) * 68, cc0 = 8 * s + lcol;
                a[i][0] = As[r0 + cc0];           a[i][1] = As[r0 + 8 * 68 + cc0];
                a[i][2] = As[r0 + cc0 + 4];       a[i][3] = As[r0 + 8 * 68 + cc0 + 4];
            }
            int cr = (cw * 8 + lrow) * 68;
            bb[0] = Bs[cr + 8 * s + lcol];
            bb[1] = Bs[cr + 8 * s + lcol + 4];
            #pragma unroll
            for (int i = 0; i < 2; i++)
                mma8(acc[i], a[i][0], a[i][1], a[i][2], a[i][3], bb[0], bb[1]);
        }
    }

    // Stage D[64d][32c] in smem.
    #pragma unroll
    for (int i = 0; i < 2; i++) {
        int d = m0w + 16 * i + lrow;
        int c = cw * 8 + 2 * lcol;
        S[d * 33 + c]           = acc[i][0];
        S[d * 33 + c + 1]       = acc[i][1];
        S[(d + 8) * 33 + c]     = acc[i][2];
        S[(d + 8) * 33 + c + 1] = acc[i][3];
    }
    __syncthreads();

    // Transposed bf16 write with bias: 32c x 8 d-chunks, 1 uint4/thread.
    {
        int c = tid >> 3, dch = tid & 7;
        int d0 = dch * 8;
        float bvv = bvS[c];
        unsigned w[4];
        #pragma unroll
        for (int u = 0; u < 4; u++) {
            float v0 = S[(d0 + 2 * u) * 33 + c]     + bvv * ksS[d0 + 2 * u];
            float v1 = S[(d0 + 2 * u + 1) * 33 + c] + bvv * ksS[d0 + 2 * u + 1];
            w[u] = packbf(v0, v1);
        }
        uint4 vv; vv.x = w[0]; vv.y = w[1]; vv.z = w[2]; vv.w = w[3];
        *(uint4*)(g_KVT + ((size_t)b * CC + c0 + c) * DD + d0) = vv;
    }
}

// ---------------------------------------------------------------------------
// K4 (bf16): out[c][n] = x[c][n] + gamma*norm[n]*sum_d KVT[c][d]*QfP[d][n]
// Persistent over c: grid (32, 8) = 256 blocks, occ 2. 8 warps: 4Mx2N.
// ---------------------------------------------------------------------------
__global__ __launch_bounds__(256, 2) void k4_out(
    const float* __restrict__ x, const float* __restrict__ gamma,
    float* __restrict__ out)
{
    __shared__ __align__(16) unsigned As32[128 * 36];
    __shared__ __align__(16) unsigned Bs32[128 * 36];
    __shared__ float ksumS[64];
    __shared__ float normS[128];

    const int n0 = blockIdx.x * 128, b = blockIdx.y;
    const int tid = threadIdx.x, wid = tid >> 5, lane = tid & 31;
    const int lrow = lane >> 2, lcol = lane & 3;
    const int m0w = (wid >> 1) * 32, n0w = (wid & 1) * 64;

    const unsigned* qfp = g_QfP + (size_t)b * 32 * NN;
    const __nv_bfloat16* kvt = g_KVT + (size_t)b * CC * DD;

    #pragma unroll
    for (int r = 0; r < 16; r++) {
        int idx = tid + r * 256;
        int dlo = idx & 3, nlo = (idx >> 2) & 7;
        int dhi = (idx >> 5) & 7, nhi = idx >> 8;
        int dp = dhi * 4 + dlo, n = nhi * 8 + nlo;
        Bs32[n * 36 + dp] = qfp[(size_t)dp * NN + n0 + n];
    }
    if (tid < 64) ksumS[tid] = g_Ksum[b * DD + tid] + 1e-10f;

    uint4 kvreg[4];
    auto ldKV = [&](int c0) {
        #pragma unroll
        for (int r = 0; r < 4; r++) {
            int idx = tid + r * 256;
            int c = idx >> 3, ch = idx & 7;
            kvreg[r] = *(const uint4*)(kvt + (size_t)(c0 + c) * DD + ch * 8);
        }
    };
    auto stAs = [&]() {
        #pragma unroll
        for (int r = 0; r < 4; r++) {
            int idx = tid + r * 256;
            int c = idx >> 3, ch = idx & 7;
            *(uint4*)(As32 + c * 36 + ch * 4) = kvreg[r];
        }
    };

    ldKV(0);
    __syncthreads();

    if (tid < 128) {
        float s = 0.f;
        #pragma unroll
        for (int dp = 0; dp < 32; dp++) {
            float2 f = __bfloat1622float2(*(const __nv_bfloat162*)&Bs32[tid * 36 + dp]);
            s = fmaf(f.x, ksumS[2 * dp], s);
            s = fmaf(f.y, ksumS[2 * dp + 1], s);
        }
        normS[tid] = 1.0f / s;
    }
    const float g = gamma[0];

    for (int ct = 0; ct < CC / 128; ct++) {
        const int c0 = ct * 128;
        __syncthreads();
        stAs();
        __syncthreads();
        if (ct + 1 < CC / 128) ldKV(c0 + 128);

        float acc[2][8][4];
        #pragma unroll
        for (int i = 0; i < 2; i++)
            #pragma unroll
            for (int j = 0; j < 8; j++)
                #pragma unroll
                for (int u = 0; u < 4; u++) acc[i][j][u] = 0.f;

        #pragma unroll
        for (int s = 0; s < 4; s++) {
            unsigned a[2][4], bb[8][2];
            #pragma unroll
            for (int i = 0; i < 2; i++) {
                int r0 = (m0w + 16 * i + lrow) * 36 + 8 * s + lcol;
                a[i][0] = As32[r0];       a[i][1] = As32[r0 + 288];
                a[i][2] = As32[r0 + 4];   a[i][3] = As32[r0 + 292];
            }
            #pragma unroll
            for (int j = 0; j < 8; j++) {
                int nr = (n0w + 8 * j + lrow) * 36 + 8 * s + lcol;
                bb[j][0] = Bs32[nr]; bb[j][1] = Bs32[nr + 4];
            }
            #pragma unroll
            for (int i = 0; i < 2; i++)
                #pragma unroll
                for (int j = 0; j < 8; j++)
                    mma16(acc[i][j], a[i][0], a[i][1], a[i][2], a[i][3], bb[j][0], bb[j][1]);
        }

        #pragma unroll
        for (int i = 0; i < 2; i++) {
            int c = c0 + m0w + 16 * i + lrow;
            #pragma unroll
            for (int j = 0; j < 8; j++) {
                int nl = n0w + 8 * j + 2 * lcol;
                int n = n0 + nl;
                float2 nr = *(float2*)&normS[nl];
                const float* xp0 = x + ((size_t)b * CC + c) * NN + n;
                float*       op0 = out + ((size_t)b * CC + c) * NN + n;
                float2 xv0 = *(const float2*)xp0;
                float2 o0 = { xv0.x + g * nr.x * acc[i][j][0],
                              xv0.y + g * nr.y * acc[i][j][1] };
                *(float2*)op0 = o0;
                const float* xp1 = x + ((size_t)b * CC + c + 8) * NN + n;
                float*       op1 = out + ((size_t)b * CC + c + 8) * NN + n;
                float2 xv1 = *(const float2*)xp1;
                float2 o1 = { xv1.x + g * nr.x * acc[i][j][2],
                              xv1.y + g * nr.y * acc[i][j][3] };
                *(float2*)op1 = o1;
            }
        }
    }
}

// ---------------------------------------------------------------------------
extern "C" void kernel_launch(void* const* d_in, const int* in_sizes, int n_in,
                              void* d_out, int out_size)
{
    const float* x     = (const float*)d_in[0];
    const float* wq    = (const float*)d_in[1];
    const float* bq    = (const float*)d_in[2];
    const float* wk    = (const float*)d_in[3];
    const float* bk    = (const float*)d_in[4];
    const float* wv    = (const float*)d_in[5];
    const float* bv    = (const float*)d_in[6];
    const float* gamma = (const float*)d_in[7];
    float* out = (float*)d_out;

    (void)in_sizes; (void)n_in; (void)out_size;

    cudaFuncSetAttribute(k1_qk, cudaFuncAttributeMaxDynamicSharedMemorySize, 37888);
    cudaFuncSetAttribute(k2_kx, cudaFuncAttributeMaxDynamicSharedMemorySize, 55296);

    void* ksum_ptr = nullptr;
    cudaGetSymbolAddress(&ksum_ptr, g_Ksum);
    cudaMemsetAsync(ksum_ptr, 0, BB * DD * sizeof(float));
    void* kx_ptr = nullptr;
    cudaGetSymbolAddress(&kx_ptr, g_KX);
    cudaMemsetAsync(kx_ptr, 0, BB * DD * CC * sizeof(float));

    k1_qk <<<dim3(NN / 128, BB),          256, 37888>>>(x, wq, bq, wk, bk);
    k2_kx <<<dim3(CC / 128, BB, KSPLIT),  256, 55296>>>(x);
    k3_kv <<<dim3(CC / 32, BB),           256>>>(wv, bv);
    k4_out<<<dim3(NN / 128, BB),          256>>>(x, gamma, out);
}

// round 15
// speedup vs baseline: 1.1372x; 1.0582x over previous
#include <cuda_runtime.h>
#include <cuda_bf16.h>

#define BB 8
#define CC 512
#define DD 64
#define NN 4096
#define KSPLIT 8      // k2 split-K over n
#define ESPLIT 8      // k3 split over e

// Scratch (device globals). ~26 MB.
__device__ unsigned g_QfP[BB * 32 * NN];            // delu(Q) bf16 pairs [b][d/2][n]
__device__ __nv_bfloat16 g_Kf[BB * DD * NN];        // delu(K) [b][d][n]
__device__ float g_Ksum[BB * DD];
__device__ float g_KXp[KSPLIT * BB * DD * CC];      // split-K partials of Kf@X^T
__device__ __nv_bfloat16 g_KVpB[ESPLIT * BB * DD * CC];  // bf16 e-split partials
__device__ __nv_bfloat16 g_KVT[BB * CC * DD];       // final KV^T [b][c][d]

__device__ __forceinline__ float delu_f(float v) {
    return v > 0.f ? fmaf(10.f, v, 1.f) : __expf(10.f * v);
}
__device__ __forceinline__ float tf32_rna(float f) {
    unsigned u;
    asm("cvt.rna.tf32.f32 %0, %1;" : "=r"(u) : "f"(f));
    return __uint_as_float(u);
}
__device__ __forceinline__ unsigned packbf(float lo, float hi) {
    __nv_bfloat162 h = __floats2bfloat162_rn(lo, hi);
    return *(unsigned*)&h;
}
// tf32 m16n8k8
__device__ __forceinline__ void mma8(float c[4], float a0, float a1, float a2, float a3,
                                     float b0, float b1) {
    unsigned A0 = __float_as_uint(a0), A1 = __float_as_uint(a1);
    unsigned A2 = __float_as_uint(a2), A3 = __float_as_uint(a3);
    unsigned B0 = __float_as_uint(b0), B1 = __float_as_uint(b1);
    asm volatile(
        "mma.sync.aligned.m16n8k8.row.col.f32.tf32.tf32.f32 "
        "{%0,%1,%2,%3}, {%4,%5,%6,%7}, {%8,%9}, {%0,%1,%2,%3};"
        : "+f"(c[0]), "+f"(c[1]), "+f"(c[2]), "+f"(c[3])
        : "r"(A0), "r"(A1), "r"(A2), "r"(A3), "r"(B0), "r"(B1));
}
// bf16 m16n8k16
__device__ __forceinline__ void mma16(float c[4], unsigned a0, unsigned a1,
                                      unsigned a2, unsigned a3,
                                      unsigned b0, unsigned b1) {
    asm volatile(
        "mma.sync.aligned.m16n8k16.row.col.f32.bf16.bf16.f32 "
        "{%0,%1,%2,%3}, {%4,%5,%6,%7}, {%8,%9}, {%0,%1,%2,%3};"
        : "+f"(c[0]), "+f"(c[1]), "+f"(c[2]), "+f"(c[3])
        : "r"(a0), "r"(a1), "r"(a2), "r"(a3), "r"(b0), "r"(b1));
}
// ldmatrix m8n8.x4 b16
__device__ __forceinline__ void ldsm4(unsigned& r0, unsigned& r1, unsigned& r2,
                                      unsigned& r3, unsigned saddr) {
    asm volatile(
        "ldmatrix.sync.aligned.m8n8.x4.shared.b16 {%0,%1,%2,%3}, [%4];"
        : "=r"(r0), "=r"(r1), "=r"(r2), "=r"(r3) : "r"(saddr));
}

// ---------------------------------------------------------------------------
// K1 (bf16, fused Q+K + Ksum): [wq;wk](128x512) @ X(512x4096) + bias -> delu
// Block 128x128, Kchunk=32, 16 iters, 8 warps (2Mx4N). grid (32, 8).
// Ping-pong double buffered. Buf (u32) = 4736; 37,888 B dynamic smem.
// ---------------------------------------------------------------------------
#define K1_BUF 4736
__global__ __launch_bounds__(256, 2) void k1_qk(
    const float* __restrict__ x,  const float* __restrict__ wq,
    const float* __restrict__ bq, const float* __restrict__ wk,
    const float* __restrict__ bk)
{
    extern __shared__ unsigned su[];
    const int b = blockIdx.y;
    const int n0 = blockIdx.x * 128;
    const int tid = threadIdx.x, wid = tid >> 5, lane = tid & 31;
    const int lrow = lane >> 2, lcol = lane & 3;
    const int m0w = (wid >> 2) * 64, n0w = (wid & 3) * 32;

    float acc[4][4][4];
    #pragma unroll
    for (int i = 0; i < 4; i++)
        #pragma unroll
        for (int j = 0; j < 4; j++)
            #pragma unroll
            for (int u = 0; u < 4; u++) acc[i][j][u] = 0.f;

    const float* xb = x + (size_t)b * CC * NN;
    const int arow = tid >> 1, ak16 = (tid & 1) * 16;
    const float* wrow = (arow < 64) ? (wq + (size_t)arow * CC)
                                    : (wk + (size_t)(arow - 64) * CC);

    float4 pa[4];
    float4 pb[2][2];
    auto ldTiles = [&](int k0) {
        #pragma unroll
        for (int t = 0; t < 4; t++)
            pa[t] = *(const float4*)(wrow + k0 + ak16 + 4 * t);
        #pragma unroll
        for (int r = 0; r < 2; r++) {
            int idx = tid + r * 256;
            int kk = idx >> 5, nch = idx & 31;
            pb[r][0] = *(const float4*)(xb + (size_t)(k0 + 2 * kk) * NN + n0 + 4 * nch);
            pb[r][1] = *(const float4*)(xb + (size_t)(k0 + 2 * kk + 1) * NN + n0 + 4 * nch);
        }
    };
    auto stTiles = [&](unsigned* buf) {
        unsigned* A = buf; unsigned* B = buf + 2560;
        const float* f = (const float*)pa;
        unsigned wa[8];
        #pragma unroll
        for (int t = 0; t < 8; t++) wa[t] = packbf(f[2 * t], f[2 * t + 1]);
        *(uint4*)(A + arow * 20 + (tid & 1) * 8)     = *(uint4*)&wa[0];
        *(uint4*)(A + arow * 20 + (tid & 1) * 8 + 4) = *(uint4*)&wa[4];
        #pragma unroll
        for (int r = 0; r < 2; r++) {
            int idx = tid + r * 256;
            int kk = idx >> 5, nch = idx & 31;
            const float* fa = (const float*)&pb[r][0];
            const float* fb = (const float*)&pb[r][1];
            unsigned wb[4];
            #pragma unroll
            for (int t = 0; t < 4; t++) wb[t] = packbf(fa[t], fb[t]);
            *(uint4*)(B + kk * 136 + nch * 4) = *(uint4*)&wb[0];
        }
    };

    ldTiles(0);
    stTiles(su);
    __syncthreads();

    int ph = 0;
    for (int k0 = 0; k0 < CC; k0 += 32, ph ^= 1) {
        unsigned* cur = su + ph * K1_BUF;
        unsigned* nxt = su + (ph ^ 1) * K1_BUF;
        const bool more = (k0 + 32 < CC);
        if (more) ldTiles(k0 + 32);

        unsigned* A = cur; unsigned* B = cur + 2560;
        #pragma unroll
        for (int s = 0; s < 2; s++) {
            unsigned a[4][4], bb[4][2];
            #pragma unroll
            for (int i = 0; i < 4; i++) {
                int r0 = (m0w + 16 * i + lrow) * 20 + 8 * s;
                a[i][0] = A[r0 + lcol];       a[i][1] = A[r0 + 160 + lcol];
                a[i][2] = A[r0 + lcol + 4];   a[i][3] = A[r0 + 160 + lcol + 4];
            }
            #pragma unroll
            for (int j = 0; j < 4; j++) {
                int n = n0w + 8 * j + lrow;
                bb[j][0] = B[(8 * s + lcol) * 136 + n];
                bb[j][1] = B[(8 * s + lcol + 4) * 136 + n];
            }
            #pragma unroll
            for (int i = 0; i < 4; i++)
                #pragma unroll
                for (int j = 0; j < 4; j++)
                    mma16(acc[i][j], a[i][0], a[i][1], a[i][2], a[i][3], bb[j][0], bb[j][1]);
        }
        if (more) stTiles(nxt);
        __syncthreads();
    }

    const bool isK = (m0w == 64);
    #pragma unroll
    for (int i = 0; i < 4; i++) {
        int m = m0w + 16 * i + lrow;
        int mm = m & 63;
        float bi0 = isK ? bk[mm] : bq[mm];
        float bi1 = isK ? bk[mm + 8] : bq[mm + 8];
        float ks_lo = 0.f, ks_hi = 0.f;
        #pragma unroll
        for (int j = 0; j < 4; j++) {
            int n = n0 + n0w + 8 * j + 2 * lcol;
            float d0 = delu_f(acc[i][j][0] + bi0);
            float d1 = delu_f(acc[i][j][1] + bi0);
            float d2 = delu_f(acc[i][j][2] + bi1);
            float d3 = delu_f(acc[i][j][3] + bi1);
            if (isK) {
                __nv_bfloat16* dst = g_Kf + (size_t)b * DD * NN;
                *(__nv_bfloat162*)(dst + (size_t)mm * NN + n) = __floats2bfloat162_rn(d0, d1);
                *(__nv_bfloat162*)(dst + (size_t)(mm + 8) * NN + n) = __floats2bfloat162_rn(d2, d3);
                ks_lo += d0 + d1;
                ks_hi += d2 + d3;
            } else {
                float e0 = __shfl_xor_sync(0xFFFFFFFFu, d0, 4);
                float e1 = __shfl_xor_sync(0xFFFFFFFFu, d1, 4);
                float e2 = __shfl_xor_sync(0xFFFFFFFFu, d2, 4);
                float e3 = __shfl_xor_sync(0xFFFFFFFFu, d3, 4);
                unsigned w0, w1;
                int dp;
                if ((lrow & 1) == 0) {
                    w0 = packbf(d0, e0); w1 = packbf(d1, e1);
                    dp = mm >> 1;
                } else {
                    w0 = packbf(e2, d2); w1 = packbf(e3, d3);
                    dp = ((mm - 1) >> 1) + 4;
                }
                uint2 v; v.x = w0; v.y = w1;
                *(uint2*)(g_QfP + (size_t)b * 32 * NN + (size_t)dp * NN + n) = v;
            }
        }
        if (isK) {
            ks_lo += __shfl_xor_sync(0xFFFFFFFFu, ks_lo, 1);
            ks_lo += __shfl_xor_sync(0xFFFFFFFFu, ks_lo, 2);
            ks_hi += __shfl_xor_sync(0xFFFFFFFFu, ks_hi, 1);
            ks_hi += __shfl_xor_sync(0xFFFFFFFFu, ks_hi, 2);
            if (lcol == 0) {
                atomicAdd(&g_Ksum[b * DD + mm], ks_lo);
                atomicAdd(&g_Ksum[b * DD + mm + 8], ks_hi);
            }
        }
    }
}

// ---------------------------------------------------------------------------
// K2 (bf16): KXp[s][b][d][e] = sum_{n in split} Kf[d][n]*x[e][n]
// Block 64x128(e), Kchunk=64 halves, K=512/split (8 iters). grid (4, 8, 8)=256.
// Buf=6912 u32; double buffer 55,296 B. Ping-pong, one sync per iter.
// ---------------------------------------------------------------------------
#define K2_BUF 6912
__global__ __launch_bounds__(256, 2) void k2_kx(const float* __restrict__ x)
{
    extern __shared__ unsigned su[];
    const int e0 = blockIdx.x * 128, b = blockIdx.y, sp = blockIdx.z;
    const int nbase = sp * (NN / KSPLIT);
    const int tid = threadIdx.x, wid = tid >> 5, lane = tid & 31;
    const int lrow = lane >> 2, lcol = lane & 3;
    const int m0w = (wid >> 2) * 32, e0w = (wid & 3) * 32;

    float acc[2][4][4];
    #pragma unroll
    for (int i = 0; i < 2; i++)
        #pragma unroll
        for (int j = 0; j < 4; j++)
            #pragma unroll
            for (int u = 0; u < 4; u++) acc[i][j][u] = 0.f;

    const __nv_bfloat16* kf = g_Kf + (size_t)b * DD * NN + nbase;
    const float* xb = x + (size_t)b * CC * NN + nbase;
    const int ad = tid >> 3, ach = tid & 7;
    const int be = tid >> 4, bf4 = tid & 15;

    uint4 pa[2];
    unsigned pbu[8][2];
    auto ldTiles = [&](int k0) {
        pa[0] = *(const uint4*)(kf + (size_t)ad * NN + k0 + ach * 8);
        pa[1] = *(const uint4*)(kf + (size_t)(ad + 32) * NN + k0 + ach * 8);
        #pragma unroll
        for (int r = 0; r < 8; r++) {
            float4 v = *(const float4*)(xb + (size_t)(e0 + be + 16 * r) * NN + k0 + bf4 * 4);
            pbu[r][0] = packbf(v.x, v.y);
            pbu[r][1] = packbf(v.z, v.w);
        }
    };
    auto stTiles = [&](unsigned* buf) {
        unsigned* As = buf; unsigned* Bs = buf + 2304;
        *(uint4*)(As + ad * 36 + ach * 4)        = pa[0];
        *(uint4*)(As + (ad + 32) * 36 + ach * 4) = pa[1];
        #pragma unroll
        for (int r = 0; r < 8; r++) {
            Bs[(be + 16 * r) * 36 + bf4 * 2]     = pbu[r][0];
            Bs[(be + 16 * r) * 36 + bf4 * 2 + 1] = pbu[r][1];
        }
    };

    ldTiles(0);
    stTiles(su);
    __syncthreads();

    int ph = 0;
    for (int k0 = 0; k0 < NN / KSPLIT; k0 += 64, ph ^= 1) {
        unsigned* cur = su + ph * K2_BUF;
        unsigned* nxt = su + (ph ^ 1) * K2_BUF;
        const bool more = (k0 + 64 < NN / KSPLIT);
        if (more) ldTiles(k0 + 64);

        unsigned* As = cur; unsigned* Bs = cur + 2304;
        #pragma unroll
        for (int s = 0; s < 4; s++) {
            unsigned a[2][4], bb[4][2];
            #pragma unroll
            for (int i = 0; i < 2; i++) {
                int r0 = (m0w + 16 * i + lrow) * 36 + 8 * s + lcol;
                a[i][0] = As[r0];           a[i][1] = As[r0 + 288];
                a[i][2] = As[r0 + 4];       a[i][3] = As[r0 + 292];
            }
            #pragma unroll
            for (int j = 0; j < 4; j++) {
                int er = (e0w + 8 * j + lrow) * 36 + 8 * s + lcol;
                bb[j][0] = Bs[er]; bb[j][1] = Bs[er + 4];
            }
            #pragma unroll
            for (int i = 0; i < 2; i++)
                #pragma unroll
                for (int j = 0; j < 4; j++)
                    mma16(acc[i][j], a[i][0], a[i][1], a[i][2], a[i][3], bb[j][0], bb[j][1]);
        }
        if (more) stTiles(nxt);
        __syncthreads();
    }

    float* dst = g_KXp + (size_t)(sp * BB + b) * DD * CC;
    #pragma unroll
    for (int i = 0; i < 2; i++) {
        int d = m0w + 16 * i + lrow;
        #pragma unroll
        for (int j = 0; j < 4; j++) {
            int e = e0 + e0w + 8 * j + 2 * lcol;
            float2 v0 = { acc[i][j][0], acc[i][j][1] };
            *(float2*)(dst + (size_t)d * CC + e) = v0;
            float2 v1 = { acc[i][j][2], acc[i][j][3] };
            *(float2*)(dst + (size_t)(d + 8) * CC + e) = v1;
        }
    }
}

// ---------------------------------------------------------------------------
// K3 (tf32, fused partial-sum): KVpB[esp][b][d][c] (bf16) =
//     sum_{e in 64-slice} (sum_sp KXp[sp][b][d][e]) * wv[c][e]
// grid (4c, 8b, ESPLIT=8e) = 256 blocks. Single 64-wide mma phase, no K-loop.
// smem: As[64][68] + Bs[128][68] fp32 = 52,224 B dynamic.
// ---------------------------------------------------------------------------
__global__ __launch_bounds__(256) void k3_kv(const float* __restrict__ wv)
{
    extern __shared__ float sf[];
    float* As = sf;              // [64][68]
    float* Bs = sf + 64 * 68;    // [128][68]
    const int c0 = blockIdx.x * 128, b = blockIdx.y, esp = blockIdx.z;
    const int ebase = esp * 64;
    const int tid = threadIdx.x, wid = tid >> 5, lane = tid & 31;
    const int lrow = lane >> 2, lcol = lane & 3;
    const int m0w = (wid >> 2) * 32, c0w = (wid & 3) * 32;

    #pragma unroll
    for (int r = 0; r < 4; r++) {
        int idx = tid + r * 256;
        int d = idx >> 4, ch = (idx & 15) * 4;
        float4 s = *(const float4*)(g_KXp + ((size_t)b * DD + d) * CC + ebase + ch);
        #pragma unroll
        for (int sp = 1; sp < KSPLIT; sp++) {
            float4 v = *(const float4*)(g_KXp +
                ((size_t)(sp * BB + b) * DD + d) * CC + ebase + ch);
            s.x += v.x; s.y += v.y; s.z += v.z; s.w += v.w;
        }
        As[d * 68 + ch + 0] = tf32_rna(s.x);
        As[d * 68 + ch + 1] = tf32_rna(s.y);
        As[d * 68 + ch + 2] = tf32_rna(s.z);
        As[d * 68 + ch + 3] = tf32_rna(s.w);
    }
    #pragma unroll
    for (int r = 0; r < 8; r++) {
        int idx = tid + r * 256;
        int c = idx >> 4, ch = (idx & 15) * 4;
        float4 v = *(const float4*)(wv + (size_t)(c0 + c) * CC + ebase + ch);
        Bs[c * 68 + ch + 0] = tf32_rna(v.x);
        Bs[c * 68 + ch + 1] = tf32_rna(v.y);
        Bs[c * 68 + ch + 2] = tf32_rna(v.z);
        Bs[c * 68 + ch + 3] = tf32_rna(v.w);
    }
    __syncthreads();

    float acc[2][4][4];
    #pragma unroll
    for (int i = 0; i < 2; i++)
        #pragma unroll
        for (int j = 0; j < 4; j++)
            #pragma unroll
            for (int u = 0; u < 4; u++) acc[i][j][u] = 0.f;

    #pragma unroll
    for (int s = 0; s < 8; s++) {
        float a[2][4], bb[4][2];
        #pragma unroll
        for (int i = 0; i < 2; i++) {
            int r0 = (m0w + 16 * i + lrow) * 68, cc0 = 8 * s + lcol;
            a[i][0] = As[r0 + cc0];           a[i][1] = As[r0 + 8 * 68 + cc0];
            a[i][2] = As[r0 + cc0 + 4];       a[i][3] = As[r0 + 8 * 68 + cc0 + 4];
        }
        #pragma unroll
        for (int j = 0; j < 4; j++) {
            int cr = (c0w + 8 * j + lrow) * 68;
            bb[j][0] = Bs[cr + 8 * s + lcol]; bb[j][1] = Bs[cr + 8 * s + lcol + 4];
        }
        #pragma unroll
        for (int i = 0; i < 2; i++)
            #pragma unroll
            for (int j = 0; j < 4; j++)
                mma8(acc[i][j], a[i][0], a[i][1], a[i][2], a[i][3], bb[j][0], bb[j][1]);
    }

    __nv_bfloat16* dst = g_KVpB + (size_t)(esp * BB + b) * DD * CC;
    #pragma unroll
    for (int i = 0; i < 2; i++) {
        int d = m0w + 16 * i + lrow;
        #pragma unroll
        for (int j = 0; j < 4; j++) {
            int c = c0 + c0w + 8 * j + 2 * lcol;
            *(unsigned*)(dst + (size_t)d * CC + c)       = packbf(acc[i][j][0], acc[i][j][1]);
            *(unsigned*)(dst + (size_t)(d + 8) * CC + c) = packbf(acc[i][j][2], acc[i][j][3]);
        }
    }
}

// ---------------------------------------------------------------------------
// sumKV: KVT[b][c][d] (bf16) = sum_esp KVpB[esp][b][d][c] + bv[c]*Ksum[b][d]
// grid (CC/32=16, BB) = 128 blocks, 256 thr. 32-wide c-slice per block.
// ---------------------------------------------------------------------------
__global__ __launch_bounds__(256) void k_sumkv(const float* __restrict__ bv)
{
    __shared__ float sm[64 * 33];
    const int c0 = blockIdx.x * 32, b = blockIdx.y;
    const int tid = threadIdx.x;

    #pragma unroll
    for (int r = 0; r < 2; r++) {
        int idx = tid + r * 256;
        int d = idx >> 3, c4 = (idx & 7) * 4;
        float s0 = 0.f, s1 = 0.f, s2 = 0.f, s3 = 0.f;
        #pragma unroll
        for (int sp = 0; sp < ESPLIT; sp++) {
            uint2 v = *(const uint2*)(g_KVpB +
                ((size_t)(sp * BB + b) * DD + d) * CC + c0 + c4);
            float2 f0 = __bfloat1622float2(*(const __nv_bfloat162*)&v.x);
            float2 f1 = __bfloat1622float2(*(const __nv_bfloat162*)&v.y);
            s0 += f0.x; s1 += f0.y; s2 += f1.x; s3 += f1.y;
        }
        float ks = g_Ksum[b * DD + d];
        float4 bvv = *(const float4*)(bv + c0 + c4);
        sm[d * 33 + c4 + 0] = s0 + bvv.x * ks;
        sm[d * 33 + c4 + 1] = s1 + bvv.y * ks;
        sm[d * 33 + c4 + 2] = s2 + bvv.z * ks;
        sm[d * 33 + c4 + 3] = s3 + bvv.w * ks;
    }
    __syncthreads();

    {
        int c = tid >> 3, dch = tid & 7;
        int d0 = dch * 8;
        unsigned w[4];
        #pragma unroll
        for (int u = 0; u < 4; u++)
            w[u] = packbf(sm[(d0 + 2 * u) * 33 + c], sm[(d0 + 2 * u + 1) * 33 + c]);
        uint4 vv; vv.x = w[0]; vv.y = w[1]; vv.z = w[2]; vv.w = w[3];
        *(uint4*)(g_KVT + ((size_t)b * CC + c0 + c) * DD + d0) = vv;
    }
}

// ---------------------------------------------------------------------------
// K4 (bf16 + ldmatrix): out[c][n] = x[c][n] + gamma*norm[n]*sum_d KVT[c][d]*QfP[d][n]
// Persistent over c: grid (32, 8) = 256 blocks, occ 2. 8 warps: 4Mx2N.
// Fragment gathers via LDSM.x4 (6 per s-step vs 24 scalar LDS).
// ---------------------------------------------------------------------------
__global__ __launch_bounds__(256, 2) void k4_out(
    const float* __restrict__ x, const float* __restrict__ gamma,
    float* __restrict__ out)
{
    __shared__ __align__(16) unsigned As32[128 * 36];
    __shared__ __align__(16) unsigned Bs32[128 * 36];
    __shared__ float ksumS[64];
    __shared__ float normS[128];

    const int n0 = blockIdx.x * 128, b = blockIdx.y;
    const int tid = threadIdx.x, wid = tid >> 5, lane = tid & 31;
    const int lrow = lane >> 2, lcol = lane & 3;
    const int m0w = (wid >> 1) * 32, n0w = (wid & 1) * 64;

    const unsigned* qfp = g_QfP + (size_t)b * 32 * NN;
    const __nv_bfloat16* kvt = g_KVT + (size_t)b * CC * DD;

    const unsigned asBase = (unsigned)__cvta_generic_to_shared(As32);
    const unsigned bsBase = (unsigned)__cvta_generic_to_shared(Bs32);
    // LDSM lane-address components.
    const int aRow  = (lane & 7) + 8 * ((lane >> 3) & 1);   // row within 16-row group
    const int aColH = 4 * (lane >> 4);                       // u32 col half (0 or 4)
    const int bRow  = lane & 7;
    const int bJsel = (lane >> 4) & 1;                       // j offset (0/1)
    const int bColH = 4 * ((lane >> 3) & 1);                 // u32 col half

    #pragma unroll
    for (int r = 0; r < 16; r++) {
        int idx = tid + r * 256;
        int dlo = idx & 3, nlo = (idx >> 2) & 7;
        int dhi = (idx >> 5) & 7, nhi = idx >> 8;
        int dp = dhi * 4 + dlo, n = nhi * 8 + nlo;
        Bs32[n * 36 + dp] = qfp[(size_t)dp * NN + n0 + n];
    }
    if (tid < 64) ksumS[tid] = g_Ksum[b * DD + tid] + 1e-10f;

    uint4 kvreg[4];
    auto ldKV = [&](int c0) {
        #pragma unroll
        for (int r = 0; r < 4; r++) {
            int idx = tid + r * 256;
            int c = idx >> 3, ch = idx & 7;
            kvreg[r] = *(const uint4*)(kvt + (size_t)(c0 + c) * DD + ch * 8);
        }
    };
    auto stAs = [&]() {
        #pragma unroll
        for (int r = 0; r < 4; r++) {
            int idx = tid + r * 256;
            int c = idx >> 3, ch = idx & 7;
            *(uint4*)(As32 + c * 36 + ch * 4) = kvreg[r];
        }
    };

    ldKV(0);
    __syncthreads();

    if (tid < 128) {
        float s = 0.f;
        #pragma unroll
        for (int dp = 0; dp < 32; dp++) {
            float2 f = __bfloat1622float2(*(const __nv_bfloat162*)&Bs32[tid * 36 + dp]);
            s = fmaf(f.x, ksumS[2 * dp], s);
            s = fmaf(f.y, ksumS[2 * dp + 1], s);
        }
        normS[tid] = 1.0f / s;
    }
    const float g = gamma[0];

    for (int ct = 0; ct < CC / 128; ct++) {
        const int c0 = ct * 128;
        __syncthreads();
        stAs();
        __syncthreads();
        if (ct + 1 < CC / 128) ldKV(c0 + 128);

        float acc[2][8][4];
        #pragma unroll
        for (int i = 0; i < 2; i++)
            #pragma unroll
            for (int j = 0; j < 8; j++)
                #pragma unroll
                for (int u = 0; u < 4; u++) acc[i][j][u] = 0.f;

        #pragma unroll
        for (int s = 0; s < 4; s++) {
            unsigned a[2][4], bb[8][2];
            // A fragments: 2 LDSM.x4 (rows = c of KVT tile; cols = d pairs)
            #pragma unroll
            for (int i = 0; i < 2; i++) {
                unsigned addr = asBase +
                    (((m0w + 16 * i + aRow) * 36 + 8 * s + aColH) << 2);
                ldsm4(a[i][0], a[i][1], a[i][2], a[i][3], addr);
            }
            // B fragments: 4 LDSM.x4 (each covers j, j+1 for both b halves)
            #pragma unroll
            for (int jp = 0; jp < 4; jp++) {
                int j = 2 * jp;
                unsigned addr = bsBase +
                    (((n0w + 8 * (j + bJsel) + bRow) * 36 + 8 * s + bColH) << 2);
                ldsm4(bb[j][0], bb[j][1], bb[j + 1][0], bb[j + 1][1], addr);
            }
            #pragma unroll
            for (int i = 0; i < 2; i++)
                #pragma unroll
                for (int j = 0; j < 8; j++)
                    mma16(acc[i][j], a[i][0], a[i][1], a[i][2], a[i][3], bb[j][0], bb[j][1]);
        }

        #pragma unroll
        for (int i = 0; i < 2; i++) {
            int c = c0 + m0w + 16 * i + lrow;
            #pragma unroll
            for (int j = 0; j < 8; j++) {
                int nl = n0w + 8 * j + 2 * lcol;
                int n = n0 + nl;
                float2 nr = *(float2*)&normS[nl];
                const float* xp0 = x + ((size_t)b * CC + c) * NN + n;
                float*       op0 = out + ((size_t)b * CC + c) * NN + n;
                float2 xv0 = *(const float2*)xp0;
                float2 o0 = { xv0.x + g * nr.x * acc[i][j][0],
                              xv0.y + g * nr.y * acc[i][j][1] };
                *(float2*)op0 = o0;
                const float* xp1 = x + ((size_t)b * CC + c + 8) * NN + n;
                float*       op1 = out + ((size_t)b * CC + c + 8) * NN + n;
                float2 xv1 = *(const float2*)xp1;
                float2 o1 = { xv1.x + g * nr.x * acc[i][j][2],
                              xv1.y + g * nr.y * acc[i][j][3] };
                *(float2*)op1 = o1;
            }
        }
    }
}

// ---------------------------------------------------------------------------
extern "C" void kernel_launch(void* const* d_in, const int* in_sizes, int n_in,
                              void* d_out, int out_size)
{
    const float* x     = (const float*)d_in[0];
    const float* wq    = (const float*)d_in[1];
    const float* bq    = (const float*)d_in[2];
    const float* wk    = (const float*)d_in[3];
    const float* bk    = (const float*)d_in[4];
    const float* wv    = (const float*)d_in[5];
    const float* bv    = (const float*)d_in[6];
    const float* gamma = (const float*)d_in[7];
    float* out = (float*)d_out;

    (void)in_sizes; (void)n_in; (void)out_size;

    cudaFuncSetAttribute(k1_qk, cudaFuncAttributeMaxDynamicSharedMemorySize, 37888);
    cudaFuncSetAttribute(k2_kx, cudaFuncAttributeMaxDynamicSharedMemorySize, 55296);
    cudaFuncSetAttribute(k3_kv, cudaFuncAttributeMaxDynamicSharedMemorySize, 52224);

    void* ksum_ptr = nullptr;
    cudaGetSymbolAddress(&ksum_ptr, g_Ksum);
    cudaMemsetAsync(ksum_ptr, 0, BB * DD * sizeof(float));

    k1_qk  <<<dim3(NN / 128, BB),          256, 37888>>>(x, wq, bq, wk, bk);
    k2_kx  <<<dim3(CC / 128, BB, KSPLIT),  256, 55296>>>(x);
    k3_kv  <<<dim3(CC / 128, BB, ESPLIT),  256, 52224>>>(wv);
    k_sumkv<<<dim3(CC / 32, BB),           256>>>(bv);
    k4_out <<<dim3(NN / 128, BB),          256>>>(x, gamma, out);
}